// round 7
// baseline (speedup 1.0000x reference)
#include <cuda_runtime.h>
#include <cstdint>

// Problem dims (fixed by the dataset)
#define M_ROWS 2048   // B*T
#define N_CON  4096   // N concepts
#define D_DIM  1024   // D
#define TOPK   128
#define R_DIM  16
#define NRELS  8

// Scratch (device globals; no allocation allowed)
__device__ float g_scores[(size_t)M_ROWS * N_CON];   // 33.5 MB (L2-resident)
__device__ float g_att[(size_t)M_ROWS * TOPK];
__device__ int   g_idx[(size_t)M_ROWS * TOPK];
__device__ int   g_any;

// ---------------------------------------------------------------------------
// any(concept_used)
// ---------------------------------------------------------------------------
__global__ void any_kernel(const unsigned char* __restrict__ used) {
    __shared__ int f;
    if (threadIdx.x == 0) f = 0;
    __syncthreads();
    int loc = 0;
    for (int i = threadIdx.x; i < N_CON; i += blockDim.x) loc |= used[i];
    if (loc) f = 1;   // benign race: all writers write 1
    __syncthreads();
    if (threadIdx.x == 0) g_any = f;
}

// ---------------------------------------------------------------------------
// tf32 helpers
// ---------------------------------------------------------------------------
__device__ __forceinline__ float to_tf32(float f) {
    unsigned u;
    asm("cvt.rna.tf32.f32 %0, %1;" : "=r"(u) : "f"(f));
    return __uint_as_float(u);
}

__device__ __forceinline__ void mma_tf32_16x8x8(float& c0, float& c1, float& c2, float& c3,
                                                unsigned a0, unsigned a1, unsigned a2, unsigned a3,
                                                unsigned b0, unsigned b1) {
    asm volatile(
        "mma.sync.aligned.m16n8k8.row.col.f32.tf32.tf32.f32 "
        "{%0,%1,%2,%3}, {%4,%5,%6,%7}, {%8,%9}, {%0,%1,%2,%3};"
        : "+f"(c0), "+f"(c1), "+f"(c2), "+f"(c3)
        : "r"(a0), "r"(a1), "r"(a2), "r"(a3), "r"(b0), "r"(b1));
}

// ---------------------------------------------------------------------------
// scores[m][n] = dot(x[m,:], proto[n,:]) / 32
// tf32 tensor-core GEMM: block tile 128x128, K-tile 32, 8 warps (2x4),
// warp tile 64x32, mma.sync m16n8k8. Register-stage double buffering.
// Smem stride 36 floats (36 mod 32 == 4) => conflict-free fragment loads.
// ---------------------------------------------------------------------------
#define KTILE 32
#define SSTR  36

__global__ __launch_bounds__(256) void sgemm_tf32_kernel(const float* __restrict__ X,
                                                         const float* __restrict__ P) {
    __shared__ float As[128 * SSTR];
    __shared__ float Bs[128 * SSTR];

    const int tid = threadIdx.x;
    const int bm = blockIdx.y * 128;
    const int bn = blockIdx.x * 128;
    const int wid = tid >> 5;
    const int lane = tid & 31;
    const int gid = lane >> 2;     // groupID 0..7
    const int tig = lane & 3;      // thread-in-group 0..3
    const int warp_m = wid >> 2;   // 0..1  -> m base = warp_m*64
    const int warp_n = wid & 3;    // 0..3  -> n base = warp_n*32
    const int mbase = warp_m * 64;
    const int nbase = warp_n * 32;

    float acc[4][4][4];
#pragma unroll
    for (int i = 0; i < 4; i++)
#pragma unroll
        for (int j = 0; j < 4; j++)
#pragma unroll
            for (int c = 0; c < 4; c++) acc[i][j][c] = 0.f;

    // Per-thread staging assignment: 4 (row, kf) pairs covering 128x32 floats.
    int srow[4], skf[4];
#pragma unroll
    for (int j = 0; j < 4; j++) {
        const int id = tid + 256 * j;   // 0..1023
        srow[j] = id >> 3;              // 0..127
        skf[j] = (id & 7) * 4;          // 0,4,...,28
    }

    float4 xbuf[4], pbuf[4];
    // Preload tile 0
#pragma unroll
    for (int j = 0; j < 4; j++) {
        xbuf[j] = *(const float4*)(X + (size_t)(bm + srow[j]) * D_DIM + skf[j]);
        pbuf[j] = *(const float4*)(P + (size_t)(bn + srow[j]) * D_DIM + skf[j]);
    }

    for (int k0 = 0; k0 < D_DIM; k0 += KTILE) {
        // Commit staged registers to smem (with tf32 rounding)
#pragma unroll
        for (int j = 0; j < 4; j++) {
            float* as = As + srow[j] * SSTR + skf[j];
            float* bs = Bs + srow[j] * SSTR + skf[j];
            as[0] = to_tf32(xbuf[j].x); as[1] = to_tf32(xbuf[j].y);
            as[2] = to_tf32(xbuf[j].z); as[3] = to_tf32(xbuf[j].w);
            bs[0] = to_tf32(pbuf[j].x); bs[1] = to_tf32(pbuf[j].y);
            bs[2] = to_tf32(pbuf[j].z); bs[3] = to_tf32(pbuf[j].w);
        }
        __syncthreads();

        // Prefetch next tile's global data while MMAs run
        const int kn = k0 + KTILE;
        if (kn < D_DIM) {
#pragma unroll
            for (int j = 0; j < 4; j++) {
                xbuf[j] = *(const float4*)(X + (size_t)(bm + srow[j]) * D_DIM + kn + skf[j]);
                pbuf[j] = *(const float4*)(P + (size_t)(bn + srow[j]) * D_DIM + kn + skf[j]);
            }
        }

#pragma unroll
        for (int ks = 0; ks < 4; ks++) {
            const int kk = ks * 8;
            unsigned bfr[4][2];
#pragma unroll
            for (int nf = 0; nf < 4; nf++) {
                const float* bp = Bs + (nbase + nf * 8 + gid) * SSTR + kk + tig;
                bfr[nf][0] = __float_as_uint(bp[0]);
                bfr[nf][1] = __float_as_uint(bp[4]);
            }
#pragma unroll
            for (int mf = 0; mf < 4; mf++) {
                const float* ap0 = As + (mbase + mf * 16 + gid) * SSTR + kk + tig;
                const float* ap1 = ap0 + 8 * SSTR;
                unsigned a0 = __float_as_uint(ap0[0]);
                unsigned a1 = __float_as_uint(ap1[0]);
                unsigned a2 = __float_as_uint(ap0[4]);
                unsigned a3 = __float_as_uint(ap1[4]);
#pragma unroll
                for (int nf = 0; nf < 4; nf++) {
                    mma_tf32_16x8x8(acc[mf][nf][0], acc[mf][nf][1],
                                    acc[mf][nf][2], acc[mf][nf][3],
                                    a0, a1, a2, a3, bfr[nf][0], bfr[nf][1]);
                }
            }
        }
        __syncthreads();
    }

    const float scale = 0.03125f;  // 1/sqrt(1024)
#pragma unroll
    for (int mf = 0; mf < 4; mf++) {
        const int m0 = bm + mbase + mf * 16 + gid;
#pragma unroll
        for (int nf = 0; nf < 4; nf++) {
            const int n0 = bn + nbase + nf * 8 + tig * 2;
            float2 v0 = make_float2(acc[mf][nf][0] * scale, acc[mf][nf][1] * scale);
            float2 v1 = make_float2(acc[mf][nf][2] * scale, acc[mf][nf][3] * scale);
            *(float2*)(g_scores + (size_t)m0 * N_CON + n0) = v0;
            *(float2*)(g_scores + (size_t)(m0 + 8) * N_CON + n0) = v1;
        }
    }
}

// ---------------------------------------------------------------------------
// Per-row exact top-128 (MSD radix select on order-preserving uint keys),
// fused with softmax + concept-mask renormalization.
// One block (256 threads) per row; each thread owns 16 CONTIGUOUS columns
// [tid*16, tid*16+16) loaded as 4 float4 (vectorized, fully coalesced).
// ---------------------------------------------------------------------------
__global__ __launch_bounds__(256) void topk_softmax_kernel(const unsigned char* __restrict__ used) {
    const int row = blockIdx.x;
    const int tid = threadIdx.x;
    const float* srow = g_scores + (size_t)row * N_CON;

    float fv[16];
    unsigned int kv[16];
#pragma unroll
    for (int q = 0; q < 4; q++) {
        float4 v4 = *(const float4*)(srow + tid * 16 + q * 4);
        fv[q * 4 + 0] = v4.x; fv[q * 4 + 1] = v4.y;
        fv[q * 4 + 2] = v4.z; fv[q * 4 + 3] = v4.w;
    }
#pragma unroll
    for (int i = 0; i < 16; i++) {
        unsigned int u = __float_as_uint(fv[i]);
        kv[i] = (u & 0x80000000u) ? ~u : (u | 0x80000000u);
    }

    __shared__ unsigned int hist[256];
    __shared__ unsigned int s_prefix;
    __shared__ int s_krem;
    if (tid == 0) { s_prefix = 0u; s_krem = TOPK; }

    for (int shift = 24; shift >= 0; shift -= 8) {
        hist[tid] = 0;
        __syncthreads();
        const unsigned int pmask = (shift == 24) ? 0u : (0xFFFFFFFFu << (shift + 8));
        const unsigned int pfx = s_prefix;
#pragma unroll
        for (int i = 0; i < 16; i++)
            if ((kv[i] & pmask) == pfx) atomicAdd(&hist[(kv[i] >> shift) & 255u], 1u);
        __syncthreads();
        if (tid == 0) {
            int krem = s_krem;
            int cum = 0;
            int b = 255;
            for (; b > 0; b--) {
                if (cum + (int)hist[b] >= krem) break;
                cum += (int)hist[b];
            }
            s_prefix = pfx | ((unsigned int)b << shift);
            s_krem = krem - cum;
        }
        __syncthreads();
    }

    __shared__ int s_cnt;
    __shared__ float s_val[TOPK];
    __shared__ int s_sel[TOPK];
    if (tid == 0) s_cnt = 0;
    __syncthreads();
    const unsigned int T = s_prefix;
#pragma unroll
    for (int i = 0; i < 16; i++)
        if (kv[i] > T) {
            int p = atomicAdd(&s_cnt, 1);
            s_val[p] = fv[i];
            s_sel[p] = tid * 16 + i;
        }
    __syncthreads();
#pragma unroll
    for (int i = 0; i < 16; i++)
        if (kv[i] == T) {
            int p = atomicAdd(&s_cnt, 1);
            if (p < TOPK) { s_val[p] = fv[i]; s_sel[p] = tid * 16 + i; }
        }
    __syncthreads();

    // Softmax over the 128 selected values (order-independent downstream)
    __shared__ float red[256];
    float v = (tid < TOPK) ? s_val[tid] : -3.4e38f;
    red[tid] = v;
    __syncthreads();
    for (int o = 128; o > 0; o >>= 1) {
        if (tid < o) red[tid] = fmaxf(red[tid], red[tid + o]);
        __syncthreads();
    }
    const float vmax = red[0];
    __syncthreads();
    float e = (tid < TOPK) ? expf(v - vmax) : 0.f;
    red[tid] = e;
    __syncthreads();
    for (int o = 128; o > 0; o >>= 1) {
        if (tid < o) red[tid] += red[tid + o];
        __syncthreads();
    }
    const float esum = red[0];
    __syncthreads();
    float att = e / esum;

    const int sel = (tid < TOPK) ? s_sel[tid] : 0;
    float act = 0.f;
    if (tid < TOPK) act = used[sel] ? 1.f : 0.f;
    float am = att * act;
    red[tid] = am;
    __syncthreads();
    for (int o = 128; o > 0; o >>= 1) {
        if (tid < o) red[tid] += red[tid + o];
        __syncthreads();
    }
    const float msum = red[0];
    const float attm = am / fmaxf(msum, 1e-8f);
    const float outv = g_any ? attm : att;
    if (tid < TOPK) {
        g_att[(size_t)row * TOPK + tid] = outv;
        g_idx[(size_t)row * TOPK + tid] = sel;
    }
}

// ---------------------------------------------------------------------------
// Per-row low-rank relational context + proto gather + residual output.
// z[r][:] = sum_k att[k] * A[r, idx[k], :]      (split over two 64-k halves)
// ct[k]   = sum_r gains[r] * (z[r] . Bm[r, idx[k], :])
// y[d]    = x[d] + 0.1/denom * sum_k ct[k] * proto[idx[k], d]
// ---------------------------------------------------------------------------
__global__ __launch_bounds__(256) void ctx_kernel(const float* __restrict__ x,
                                                  const float* __restrict__ proto,
                                                  const float* __restrict__ A,
                                                  const float* __restrict__ Bm,
                                                  const float* __restrict__ gains,
                                                  float* __restrict__ y) {
    const int row = blockIdx.x;
    const int tid = threadIdx.x;
    __shared__ float s_att[TOPK];
    __shared__ int s_idx[TOPK];
    __shared__ float s_zp[2][NRELS * R_DIM];   // partial z per k-half
    __shared__ float s_z[NRELS * R_DIM];
    __shared__ float s_ct[TOPK];
    __shared__ float s_g[NRELS];

    if (tid < TOPK) {
        s_att[tid] = g_att[(size_t)row * TOPK + tid];
        s_idx[tid] = g_idx[(size_t)row * TOPK + tid];
    }
    if (tid < NRELS) s_g[tid] = gains[tid];
    __syncthreads();

    // z-phase: all 256 threads active. tid<128 does k in [0,64), else [64,128).
    {
        const int half = tid >> 7;            // 0 or 1
        const int t = tid & 127;              // 0..127
        const int r = t >> 4, c = t & 15;
        const int kb = half * 64;
        const float* Abase = A + ((size_t)r * N_CON) * R_DIM + c;
        float acc = 0.f;
#pragma unroll 8
        for (int k = 0; k < 64; k++)
            acc += s_att[kb + k] * Abase[(size_t)s_idx[kb + k] * R_DIM];
        s_zp[half][t] = acc;
    }
    __syncthreads();
    if (tid < NRELS * R_DIM) s_z[tid] = s_zp[0][tid] + s_zp[1][tid];
    __syncthreads();

    if (tid < TOPK) {
        const int id = s_idx[tid];
        float acc = 0.f;
#pragma unroll
        for (int r = 0; r < NRELS; r++) {
            const float4* Brow = (const float4*)(Bm + ((size_t)r * N_CON + id) * R_DIM);
            const float* zr = s_z + r * R_DIM;
            float4 b0 = Brow[0], b1 = Brow[1], b2 = Brow[2], b3 = Brow[3];
            float s = zr[0] * b0.x + zr[1] * b0.y + zr[2] * b0.z + zr[3] * b0.w
                    + zr[4] * b1.x + zr[5] * b1.y + zr[6] * b1.z + zr[7] * b1.w
                    + zr[8] * b2.x + zr[9] * b2.y + zr[10] * b2.z + zr[11] * b2.w
                    + zr[12] * b3.x + zr[13] * b3.y + zr[14] * b3.z + zr[15] * b3.w;
            acc += s_g[r] * s;
        }
        s_ct[tid] = acc;
    }
    __syncthreads();

    float denom = 0.f;
#pragma unroll
    for (int r = 0; r < NRELS; r++) denom += s_g[r];
    if (denom <= 0.f) denom = 1.f;
    const float coef = 0.1f / denom;

    float a0 = 0.f, a1 = 0.f, a2 = 0.f, a3 = 0.f;
#pragma unroll 8
    for (int k = 0; k < TOPK; k++) {
        const float w = s_ct[k];
        const float* p = proto + (size_t)s_idx[k] * D_DIM + tid;
        a0 += w * p[0];
        a1 += w * p[256];
        a2 += w * p[512];
        a3 += w * p[768];
    }
    const float* xr = x + (size_t)row * D_DIM;
    float* yr = y + (size_t)row * D_DIM;
    yr[tid]       = xr[tid]       + coef * a0;
    yr[tid + 256] = xr[tid + 256] + coef * a1;
    yr[tid + 512] = xr[tid + 512] + coef * a2;
    yr[tid + 768] = xr[tid + 768] + coef * a3;
}

// ---------------------------------------------------------------------------
extern "C" void kernel_launch(void* const* d_in, const int* in_sizes, int n_in,
                              void* d_out, int out_size) {
    (void)in_sizes; (void)n_in; (void)out_size;
    const float* x = (const float*)d_in[0];
    const unsigned char* used = (const unsigned char*)d_in[1];
    const float* proto = (const float*)d_in[2];
    const float* A = (const float*)d_in[3];
    const float* Bm = (const float*)d_in[4];
    const float* gains = (const float*)d_in[5];
    float* y = (float*)d_out;

    any_kernel<<<1, 256>>>(used);
    dim3 grid(N_CON / 128, M_ROWS / 128);
    sgemm_tf32_kernel<<<grid, 256>>>(x, proto);
    topk_softmax_kernel<<<M_ROWS, 256>>>(used);
    ctx_kernel<<<M_ROWS, 256>>>(x, proto, A, Bm, gains, y);
}

// round 10
// speedup vs baseline: 1.2314x; 1.2314x over previous
#include <cuda_runtime.h>
#include <cuda_bf16.h>
#include <cstdint>

// Problem dims (fixed by the dataset)
#define M_ROWS 2048   // B*T
#define N_CON  4096   // N concepts
#define D_DIM  1024   // D
#define TOPK   128
#define R_DIM  16
#define NRELS  8

// Scratch (device globals; no allocation allowed)
__device__ float g_scores[(size_t)M_ROWS * N_CON];   // 33.5 MB (L2-resident)
__device__ float g_att[(size_t)M_ROWS * TOPK];
__device__ int   g_idx[(size_t)M_ROWS * TOPK];
__device__ int   g_any;

// ---------------------------------------------------------------------------
// any(concept_used)
// ---------------------------------------------------------------------------
__global__ void any_kernel(const unsigned char* __restrict__ used) {
    __shared__ int f;
    if (threadIdx.x == 0) f = 0;
    __syncthreads();
    int loc = 0;
    for (int i = threadIdx.x; i < N_CON; i += blockDim.x) loc |= used[i];
    if (loc) f = 1;   // benign race: all writers write 1
    __syncthreads();
    if (threadIdx.x == 0) g_any = f;
}

// ---------------------------------------------------------------------------
// bf16 mma helper: D(16x8,f32) += A(16x16,bf16) * B(16x8,bf16)
// ---------------------------------------------------------------------------
__device__ __forceinline__ void mma_bf16_16x8x16(float& c0, float& c1, float& c2, float& c3,
                                                 unsigned a0, unsigned a1, unsigned a2, unsigned a3,
                                                 unsigned b0, unsigned b1) {
    asm volatile(
        "mma.sync.aligned.m16n8k16.row.col.f32.bf16.bf16.f32 "
        "{%0,%1,%2,%3}, {%4,%5,%6,%7}, {%8,%9}, {%0,%1,%2,%3};"
        : "+f"(c0), "+f"(c1), "+f"(c2), "+f"(c3)
        : "r"(a0), "r"(a1), "r"(a2), "r"(a3), "r"(b0), "r"(b1));
}

// ---------------------------------------------------------------------------
// scores[m][n] = dot(x[m,:], proto[n,:]) / 32
// bf16 tensor-core GEMM: block tile 128x128, K-tile 32 (= 16 bf16x2 words),
// 8 warps (2x4), warp tile 64x32, mma.sync m16n8k16, fp32 accumulate.
// Smem rows are 20 uint32 words (16 used + 4 pad). 20 mod 32 = 20 =>
// fragment-load bank = (20*gid + tig) mod 32, all 32 distinct: conflict-free.
// Register-stage double buffering of the global loads.
// ---------------------------------------------------------------------------
#define KTILE   32
#define SSTRW   20    // uint32 words per smem row

__global__ __launch_bounds__(256) void sgemm_bf16_kernel(const float* __restrict__ X,
                                                         const float* __restrict__ P) {
    __shared__ unsigned As[128 * SSTRW];
    __shared__ unsigned Bs[128 * SSTRW];

    const int tid = threadIdx.x;
    const int bm = blockIdx.y * 128;
    const int bn = blockIdx.x * 128;
    const int wid = tid >> 5;
    const int lane = tid & 31;
    const int gid = lane >> 2;     // groupID 0..7
    const int tig = lane & 3;      // thread-in-group 0..3
    const int warp_m = wid >> 2;   // 0..1
    const int warp_n = wid & 3;    // 0..3
    const int mbase = warp_m * 64;
    const int nbase = warp_n * 32;

    float acc[4][4][4];
#pragma unroll
    for (int i = 0; i < 4; i++)
#pragma unroll
        for (int j = 0; j < 4; j++)
#pragma unroll
            for (int c = 0; c < 4; c++) acc[i][j][c] = 0.f;

    // Staging: 128 rows x 8 float4 (32 floats) per matrix per K-tile.
    // Thread handles 4 float4s: id = tid + 256j; row = id>>3; f4 = id&7.
    int srow[4], sf4[4];
#pragma unroll
    for (int j = 0; j < 4; j++) {
        const int id = tid + 256 * j;
        srow[j] = id >> 3;
        sf4[j] = id & 7;
    }

    float4 xbuf[4], pbuf[4];
#pragma unroll
    for (int j = 0; j < 4; j++) {
        xbuf[j] = *(const float4*)(X + (size_t)(bm + srow[j]) * D_DIM + sf4[j] * 4);
        pbuf[j] = *(const float4*)(P + (size_t)(bn + srow[j]) * D_DIM + sf4[j] * 4);
    }

    for (int k0 = 0; k0 < D_DIM; k0 += KTILE) {
        // Commit staged registers to smem as bf16x2 words
#pragma unroll
        for (int j = 0; j < 4; j++) {
            unsigned* as = As + srow[j] * SSTRW + sf4[j] * 2;
            unsigned* bs = Bs + srow[j] * SSTRW + sf4[j] * 2;
            __nv_bfloat162 ax = __floats2bfloat162_rn(xbuf[j].x, xbuf[j].y);
            __nv_bfloat162 ay = __floats2bfloat162_rn(xbuf[j].z, xbuf[j].w);
            __nv_bfloat162 px = __floats2bfloat162_rn(pbuf[j].x, pbuf[j].y);
            __nv_bfloat162 py = __floats2bfloat162_rn(pbuf[j].z, pbuf[j].w);
            as[0] = *(unsigned*)&ax; as[1] = *(unsigned*)&ay;
            bs[0] = *(unsigned*)&px; bs[1] = *(unsigned*)&py;
        }
        __syncthreads();

        // Prefetch next K-tile while MMAs run
        const int kn = k0 + KTILE;
        if (kn < D_DIM) {
#pragma unroll
            for (int j = 0; j < 4; j++) {
                xbuf[j] = *(const float4*)(X + (size_t)(bm + srow[j]) * D_DIM + kn + sf4[j] * 4);
                pbuf[j] = *(const float4*)(P + (size_t)(bn + srow[j]) * D_DIM + kn + sf4[j] * 4);
            }
        }

#pragma unroll
        for (int ks = 0; ks < 2; ks++) {          // two k16 steps per K-tile
            const int kwb = ks * 8;               // word base within row
            unsigned bfr[4][2];
#pragma unroll
            for (int nf = 0; nf < 4; nf++) {
                const unsigned* bp = Bs + (nbase + nf * 8 + gid) * SSTRW + kwb + tig;
                bfr[nf][0] = bp[0];
                bfr[nf][1] = bp[4];
            }
#pragma unroll
            for (int mf = 0; mf < 4; mf++) {
                const unsigned* ap0 = As + (mbase + mf * 16 + gid) * SSTRW + kwb + tig;
                const unsigned* ap1 = ap0 + 8 * SSTRW;
                unsigned a0 = ap0[0];
                unsigned a1 = ap1[0];
                unsigned a2 = ap0[4];
                unsigned a3 = ap1[4];
#pragma unroll
                for (int nf = 0; nf < 4; nf++) {
                    mma_bf16_16x8x16(acc[mf][nf][0], acc[mf][nf][1],
                                     acc[mf][nf][2], acc[mf][nf][3],
                                     a0, a1, a2, a3, bfr[nf][0], bfr[nf][1]);
                }
            }
        }
        __syncthreads();
    }

    const float scale = 0.03125f;  // 1/sqrt(1024)
#pragma unroll
    for (int mf = 0; mf < 4; mf++) {
        const int m0 = bm + mbase + mf * 16 + gid;
#pragma unroll
        for (int nf = 0; nf < 4; nf++) {
            const int n0 = bn + nbase + nf * 8 + tig * 2;
            float2 v0 = make_float2(acc[mf][nf][0] * scale, acc[mf][nf][1] * scale);
            float2 v1 = make_float2(acc[mf][nf][2] * scale, acc[mf][nf][3] * scale);
            *(float2*)(g_scores + (size_t)m0 * N_CON + n0) = v0;
            *(float2*)(g_scores + (size_t)(m0 + 8) * N_CON + n0) = v1;
        }
    }
}

// ---------------------------------------------------------------------------
// Per-row exact top-128 (MSD radix select on order-preserving uint keys),
// fused with softmax + concept-mask renormalization.
// One block (256 threads) per row; each thread owns 16 CONTIGUOUS columns
// [tid*16, tid*16+16) loaded as 4 float4 (vectorized, fully coalesced).
// ---------------------------------------------------------------------------
__global__ __launch_bounds__(256) void topk_softmax_kernel(const unsigned char* __restrict__ used) {
    const int row = blockIdx.x;
    const int tid = threadIdx.x;
    const float* srow = g_scores + (size_t)row * N_CON;

    float fv[16];
    unsigned int kv[16];
#pragma unroll
    for (int q = 0; q < 4; q++) {
        float4 v4 = *(const float4*)(srow + tid * 16 + q * 4);
        fv[q * 4 + 0] = v4.x; fv[q * 4 + 1] = v4.y;
        fv[q * 4 + 2] = v4.z; fv[q * 4 + 3] = v4.w;
    }
#pragma unroll
    for (int i = 0; i < 16; i++) {
        unsigned int u = __float_as_uint(fv[i]);
        kv[i] = (u & 0x80000000u) ? ~u : (u | 0x80000000u);
    }

    __shared__ unsigned int hist[256];
    __shared__ unsigned int s_prefix;
    __shared__ int s_krem;
    if (tid == 0) { s_prefix = 0u; s_krem = TOPK; }

    for (int shift = 24; shift >= 0; shift -= 8) {
        hist[tid] = 0;
        __syncthreads();
        const unsigned int pmask = (shift == 24) ? 0u : (0xFFFFFFFFu << (shift + 8));
        const unsigned int pfx = s_prefix;
#pragma unroll
        for (int i = 0; i < 16; i++)
            if ((kv[i] & pmask) == pfx) atomicAdd(&hist[(kv[i] >> shift) & 255u], 1u);
        __syncthreads();
        if (tid == 0) {
            int krem = s_krem;
            int cum = 0;
            int b = 255;
            for (; b > 0; b--) {
                if (cum + (int)hist[b] >= krem) break;
                cum += (int)hist[b];
            }
            s_prefix = pfx | ((unsigned int)b << shift);
            s_krem = krem - cum;
        }
        __syncthreads();
    }

    __shared__ int s_cnt;
    __shared__ float s_val[TOPK];
    __shared__ int s_sel[TOPK];
    if (tid == 0) s_cnt = 0;
    __syncthreads();
    const unsigned int T = s_prefix;
#pragma unroll
    for (int i = 0; i < 16; i++)
        if (kv[i] > T) {
            int p = atomicAdd(&s_cnt, 1);
            s_val[p] = fv[i];
            s_sel[p] = tid * 16 + i;
        }
    __syncthreads();
#pragma unroll
    for (int i = 0; i < 16; i++)
        if (kv[i] == T) {
            int p = atomicAdd(&s_cnt, 1);
            if (p < TOPK) { s_val[p] = fv[i]; s_sel[p] = tid * 16 + i; }
        }
    __syncthreads();

    // Softmax over the 128 selected values (order-independent downstream)
    __shared__ float red[256];
    float v = (tid < TOPK) ? s_val[tid] : -3.4e38f;
    red[tid] = v;
    __syncthreads();
    for (int o = 128; o > 0; o >>= 1) {
        if (tid < o) red[tid] = fmaxf(red[tid], red[tid + o]);
        __syncthreads();
    }
    const float vmax = red[0];
    __syncthreads();
    float e = (tid < TOPK) ? expf(v - vmax) : 0.f;
    red[tid] = e;
    __syncthreads();
    for (int o = 128; o > 0; o >>= 1) {
        if (tid < o) red[tid] += red[tid + o];
        __syncthreads();
    }
    const float esum = red[0];
    __syncthreads();
    float att = e / esum;

    const int sel = (tid < TOPK) ? s_sel[tid] : 0;
    float act = 0.f;
    if (tid < TOPK) act = used[sel] ? 1.f : 0.f;
    float am = att * act;
    red[tid] = am;
    __syncthreads();
    for (int o = 128; o > 0; o >>= 1) {
        if (tid < o) red[tid] += red[tid + o];
        __syncthreads();
    }
    const float msum = red[0];
    const float attm = am / fmaxf(msum, 1e-8f);
    const float outv = g_any ? attm : att;
    if (tid < TOPK) {
        g_att[(size_t)row * TOPK + tid] = outv;
        g_idx[(size_t)row * TOPK + tid] = sel;
    }
}

// ---------------------------------------------------------------------------
// Per-row low-rank relational context + proto gather + residual output.
// z[r][:] = sum_k att[k] * A[r, idx[k], :]      (split over two 64-k halves)
// ct[k]   = sum_r gains[r] * (z[r] . Bm[r, idx[k], :])
// y[d]    = x[d] + 0.1/denom * sum_k ct[k] * proto[idx[k], d]
// Proto gather vectorized: thread tid owns dims [4*tid, 4*tid+4) -> LDG.128.
// ---------------------------------------------------------------------------
__global__ __launch_bounds__(256) void ctx_kernel(const float* __restrict__ x,
                                                  const float* __restrict__ proto,
                                                  const float* __restrict__ A,
                                                  const float* __restrict__ Bm,
                                                  const float* __restrict__ gains,
                                                  float* __restrict__ y) {
    const int row = blockIdx.x;
    const int tid = threadIdx.x;
    __shared__ float s_att[TOPK];
    __shared__ int s_idx[TOPK];
    __shared__ float s_zp[2][NRELS * R_DIM];   // partial z per k-half
    __shared__ float s_z[NRELS * R_DIM];
    __shared__ float s_ct[TOPK];
    __shared__ float s_g[NRELS];

    if (tid < TOPK) {
        s_att[tid] = g_att[(size_t)row * TOPK + tid];
        s_idx[tid] = g_idx[(size_t)row * TOPK + tid];
    }
    if (tid < NRELS) s_g[tid] = gains[tid];
    __syncthreads();

    // z-phase: all 256 threads active. tid<128 does k in [0,64), else [64,128).
    {
        const int half = tid >> 7;            // 0 or 1
        const int t = tid & 127;              // 0..127
        const int r = t >> 4, c = t & 15;
        const int kb = half * 64;
        const float* Abase = A + ((size_t)r * N_CON) * R_DIM + c;
        float acc = 0.f;
#pragma unroll 8
        for (int k = 0; k < 64; k++)
            acc += s_att[kb + k] * Abase[(size_t)s_idx[kb + k] * R_DIM];
        s_zp[half][t] = acc;
    }
    __syncthreads();
    if (tid < NRELS * R_DIM) s_z[tid] = s_zp[0][tid] + s_zp[1][tid];
    __syncthreads();

    if (tid < TOPK) {
        const int id = s_idx[tid];
        float acc = 0.f;
#pragma unroll
        for (int r = 0; r < NRELS; r++) {
            const float4* Brow = (const float4*)(Bm + ((size_t)r * N_CON + id) * R_DIM);
            const float* zr = s_z + r * R_DIM;
            float4 b0 = Brow[0], b1 = Brow[1], b2 = Brow[2], b3 = Brow[3];
            float s = zr[0] * b0.x + zr[1] * b0.y + zr[2] * b0.z + zr[3] * b0.w
                    + zr[4] * b1.x + zr[5] * b1.y + zr[6] * b1.z + zr[7] * b1.w
                    + zr[8] * b2.x + zr[9] * b2.y + zr[10] * b2.z + zr[11] * b2.w
                    + zr[12] * b3.x + zr[13] * b3.y + zr[14] * b3.z + zr[15] * b3.w;
            acc += s_g[r] * s;
        }
        s_ct[tid] = acc;
    }
    __syncthreads();

    float denom = 0.f;
#pragma unroll
    for (int r = 0; r < NRELS; r++) denom += s_g[r];
    if (denom <= 0.f) denom = 1.f;
    const float coef = 0.1f / denom;

    // Proto gather: one float4 per k per thread (contiguous dims per thread)
    float a0 = 0.f, a1 = 0.f, a2 = 0.f, a3 = 0.f;
    const float* pbase = proto + 4 * tid;
#pragma unroll 8
    for (int k = 0; k < TOPK; k++) {
        const float w = s_ct[k];
        float4 p = *(const float4*)(pbase + (size_t)s_idx[k] * D_DIM);
        a0 += w * p.x;
        a1 += w * p.y;
        a2 += w * p.z;
        a3 += w * p.w;
    }
    float4 xv = *(const float4*)(x + (size_t)row * D_DIM + 4 * tid);
    float4 yv;
    yv.x = xv.x + coef * a0;
    yv.y = xv.y + coef * a1;
    yv.z = xv.z + coef * a2;
    yv.w = xv.w + coef * a3;
    *(float4*)(y + (size_t)row * D_DIM + 4 * tid) = yv;
}

// ---------------------------------------------------------------------------
extern "C" void kernel_launch(void* const* d_in, const int* in_sizes, int n_in,
                              void* d_out, int out_size) {
    (void)in_sizes; (void)n_in; (void)out_size;
    const float* x = (const float*)d_in[0];
    const unsigned char* used = (const unsigned char*)d_in[1];
    const float* proto = (const float*)d_in[2];
    const float* A = (const float*)d_in[3];
    const float* Bm = (const float*)d_in[4];
    const float* gains = (const float*)d_in[5];
    float* y = (float*)d_out;

    any_kernel<<<1, 256>>>(used);
    dim3 grid(N_CON / 128, M_ROWS / 128);
    sgemm_bf16_kernel<<<grid, 256>>>(x, proto);
    topk_softmax_kernel<<<M_ROWS, 256>>>(used);
    ctx_kernel<<<M_ROWS, 256>>>(x, proto, A, Bm, gains, y);
}